// round 12
// baseline (speedup 1.0000x reference)
#include <cuda_runtime.h>
#include <cuda_bf16.h>

// ---------------------------------------------------------------------------
// QuantumLayer: 4 qubits, 2 variational layers, B = 1e6.
//
// z_q(b) = sum_{t in 3^4} T_q[t] * prod_q basis_{t_q}(x_q),
//   basis = (1, cos x_q, sin x_q);  T[81][4] depends only on weights.
//
// Node 1 (setup, 1 block x 256): barrier-pipelined gate engine (R11) —
//   writes T into BOTH the __constant__ backing store and a __device__
//   global mirror.
// Node 2 (main): NS=2 contraction with T served from TWO ports at once:
//   even a-rows via the constant datapath (LDC.128, floor 8), odd a-rows
//   via shared memory (broadcast LDS.128, floor 4). Neither port exceeds
//   the fma-pipe floor, so ffma2 issue stays dense.
// ---------------------------------------------------------------------------

#define DIM 16

__constant__ ulonglong2 cT[81];    // .x = packed (T0,T1), .y = packed (T2,T3)
__device__   ulonglong2 g_T[81];   // global mirror (staged into shared)

// ---------------------------------------------------------------------------
// Setup kernel: one block, 256 threads, barrier-pipelined (R11 structure).
// ---------------------------------------------------------------------------
__global__ void __launch_bounds__(256)
setup_kernel(const float* __restrict__ weights, float4* __restrict__ t_out) {
    __shared__ float sRe[DIM][DIM + 1];   // [col k][row j] = Re(U[j][k]), padded
    __shared__ float sIm[DIM][DIM + 1];
    __shared__ float sG[8][8];            // per (l,q): composed 2x2 complex gate
    __shared__ float sA[4][256];          // A_q[k*16+k']
    int tid = threadIdx.x;

    // ---- Stage 0: compose G = RZ*RY*RX for the 8 (l,q) gates; init U=I ----
    if (tid < 8) {
        float thx = weights[tid * 3 + 0];
        float thy = weights[tid * 3 + 1];
        float thz = weights[tid * 3 + 2];
        float cx, sx, cy, sy, cz, sz;
        __sincosf(0.5f * thx, &sx, &cx);
        __sincosf(0.5f * thy, &sy, &cy);
        __sincosf(0.5f * thz, &sz, &cz);
        // M = RY * RX
        float m00r = cy * cx,  m00i =  sy * sx;
        float m01r = -sy * cx, m01i = -cy * sx;
        float m10r =  sy * cx, m10i = -cy * sx;
        float m11r =  cy * cx, m11i = -sy * sx;
        // G row0 = (cz - i sz) * m0?,  row1 = (cz + i sz) * m1?
        sG[tid][0] = cz * m00r + sz * m00i;  sG[tid][1] = cz * m00i - sz * m00r;
        sG[tid][2] = cz * m01r + sz * m01i;  sG[tid][3] = cz * m01i - sz * m01r;
        sG[tid][4] = cz * m10r - sz * m10i;  sG[tid][5] = cz * m10i + sz * m10r;
        sG[tid][6] = cz * m11r - sz * m11i;  sG[tid][7] = cz * m11i + sz * m11r;
    }
    {   // identity init: thread t = (k, j)
        int k = tid >> 4, j = tid & 15;
        sRe[k][j] = (j == k) ? 1.0f : 0.0f;
        sIm[k][j] = 0.0f;
    }
    __syncthreads();

    // ---- Layers: 4 gate stages each, then one permutation stage ----------
#pragma unroll
    for (int l = 0; l < 2; l++) {
#pragma unroll
        for (int q = 0; q < 4; q++) {
            if (tid < 128) {
                const int mask = 8 >> q;
                int k = tid >> 3, rr = tid & 7;
                int j0 = ((rr & ~(mask - 1)) << 1) | (rr & (mask - 1));
                int j1 = j0 | mask;
                const float* G = sG[l * 4 + q];
                float a0r = sRe[k][j0], a0i = sIm[k][j0];
                float a1r = sRe[k][j1], a1i = sIm[k][j1];
                sRe[k][j0] = G[0]*a0r - G[1]*a0i + G[2]*a1r - G[3]*a1i;
                sIm[k][j0] = G[0]*a0i + G[1]*a0r + G[2]*a1i + G[3]*a1r;
                sRe[k][j1] = G[4]*a0r - G[5]*a0i + G[6]*a1r - G[7]*a1i;
                sIm[k][j1] = G[4]*a0i + G[5]*a0r + G[6]*a1i + G[7]*a1r;
            }
            __syncthreads();
        }
        // CNOT ring (0,1),(1,2),(2,3),(3,0) folded into one permutation.
        {
            int k = tid >> 4, j = tid & 15;
            float vr = sRe[k][j], vi = sIm[k][j];
            int jp = j;
#pragma unroll
            for (int e = 0; e < 4; e++) {
                int cm = 8 >> e, tm = 8 >> ((e + 1) & 3);
                if (jp & cm) jp ^= tm;
            }
            __syncthreads();
            sRe[k][jp] = vr;
            sIm[k][jp] = vi;
            __syncthreads();
        }
    }

    // ---- Fold encoding phase (-i)^popc(k) into column k -------------------
    {
        int k = tid >> 4, j = tid & 15;
        int pc = __popc(k) & 3;
        float pr = (pc == 0) ? 1.0f : (pc == 2) ? -1.0f : 0.0f;
        float pi = (pc == 1) ? -1.0f : (pc == 3) ? 1.0f : 0.0f;
        float vr = sRe[k][j], vi = sIm[k][j];
        sRe[k][j] = vr * pr - vi * pi;
        sIm[k][j] = vr * pi + vi * pr;
    }
    __syncthreads();

    // ---- Phase 2: thread (k,k') computes A_q[k,k'] ------------------------
    {
        int k = tid >> 4, kp = tid & 15;
        float a0 = 0.f, a1 = 0.f, a2 = 0.f, a3 = 0.f;
#pragma unroll
        for (int j = 0; j < DIM; j++) {
            float p = sRe[k][j] * sRe[kp][j] + sIm[k][j] * sIm[kp][j];
            a0 += (j & 8) ? -p : p;
            a1 += (j & 4) ? -p : p;
            a2 += (j & 2) ? -p : p;
            a3 += (j & 1) ? -p : p;
        }
        sA[0][tid] = a0; sA[1][tid] = a1; sA[2][tid] = a2; sA[3][tid] = a3;
    }
    __syncthreads();

    // ---- Phase 3: threads 0-80 compute T[t] -> const backing + mirror -----
    if (tid < 81) {
        int t0 = tid / 27, t1 = (tid / 9) % 3, t2 = (tid / 3) % 3, t3 = tid % 3;
        int mix = 0, sgn = 0;
        if (t0 == 2) mix |= 8; else if (t0 == 1) sgn |= 8;
        if (t1 == 2) mix |= 4; else if (t1 == 1) sgn |= 4;
        if (t2 == 2) mix |= 2; else if (t2 == 1) sgn |= 2;
        if (t3 == 2) mix |= 1; else if (t3 == 1) sgn |= 1;

        float r0 = 0.f, r1 = 0.f, r2 = 0.f, r3 = 0.f;
#pragma unroll
        for (int k = 0; k < DIM; k++) {
            int idx = k * DIM + (k ^ mix);
            float s = (__popc(k & sgn) & 1) ? -1.0f : 1.0f;
            r0 += s * sA[0][idx];
            r1 += s * sA[1][idx];
            r2 += s * sA[2][idx];
            r3 += s * sA[3][idx];
        }
        const float sc = 1.0f / 16.0f;
        float4 t4 = make_float4(r0 * sc, r1 * sc, r2 * sc, r3 * sc);
        t_out[tid] = t4;                 // constant backing store
        ((float4*)g_T)[tid] = t4;        // global mirror for shared staging
    }
}

// ---------------------------------------------------------------------------
// Packed f32x2 helpers
// ---------------------------------------------------------------------------
__device__ __forceinline__ void ffma2(unsigned long long& d,
                                      unsigned long long a,
                                      unsigned long long b) {
    asm("fma.rn.f32x2 %0, %1, %2, %0;" : "+l"(d) : "l"(a), "l"(b));
}

__device__ __forceinline__ unsigned long long pack_dup(float v) {
    unsigned long long out;
    unsigned int u = __float_as_uint(v);
    asm("mov.b64 %0, {%1, %1};" : "=l"(out) : "r"(u));
    return out;
}

__device__ __forceinline__ void unpack2(unsigned long long v, float& lo, float& hi) {
    unsigned int a, b;
    asm("mov.b64 {%0, %1}, %2;" : "=r"(a), "=r"(b) : "l"(v));
    lo = __uint_as_float(a);
    hi = __uint_as_float(b);
}

// ---------------------------------------------------------------------------
// Main kernel: 2 samples/thread; T from const (even a-rows) + shared (odd).
// ---------------------------------------------------------------------------
__global__ void __launch_bounds__(128)
qlayer_kernel(const float4* __restrict__ in, float4* __restrict__ out, int nb) {
    __shared__ ulonglong2 sT[81];
    if (threadIdx.x < 81) sT[threadIdx.x] = g_T[threadIdx.x];
    __syncthreads();

    int p = blockIdx.x * blockDim.x + threadIdx.x;   // pair index
    int b0 = 2 * p;
    if (b0 >= nb) return;
    bool hasB = (b0 + 1) < nb;

    float4 xA = in[b0];
    float4 xB = hasB ? in[b0 + 1] : xA;

    float cA0, sA0, cA1, sA1, cA2, sA2, cA3, sA3;
    __sincosf(xA.x, &sA0, &cA0);
    __sincosf(xA.y, &sA1, &cA1);
    __sincosf(xA.z, &sA2, &cA2);
    __sincosf(xA.w, &sA3, &cA3);
    float cB0, sB0, cB1, sB1, cB2, sB2, cB3, sB3;
    __sincosf(xB.x, &sB0, &cB0);
    __sincosf(xB.y, &sB1, &cB1);
    __sincosf(xB.z, &sB2, &cB2);
    __sincosf(xB.w, &sB3, &cB3);

    float abA[9] = { 1.f, cA1, sA1, cA0, cA0 * cA1, cA0 * sA1, sA0, sA0 * cA1, sA0 * sA1 };
    float abB[9] = { 1.f, cB1, sB1, cB0, cB0 * cB1, cB0 * sB1, sB0, sB0 * cB1, sB0 * sB1 };
    float cdAs[9] = { 1.f, cA3, sA3, cA2, cA2 * cA3, cA2 * sA3, sA2, sA2 * cA3, sA2 * sA3 };
    float cdBs[9] = { 1.f, cB3, sB3, cB2, cB2 * cB3, cB2 * sB3, sB2, sB2 * cB3, sB2 * sB3 };
    unsigned long long cdA[9], cdB[9];
#pragma unroll
    for (int c = 0; c < 9; c++) { cdA[c] = pack_dup(cdAs[c]); cdB[c] = pack_dup(cdBs[c]); }

    unsigned long long zA01 = 0ull, zA23 = 0ull, zB01 = 0ull, zB23 = 0ull;
#pragma unroll
    for (int a = 0; a < 9; a++) {
        unsigned long long vA01 = 0ull, vA23 = 0ull, vB01 = 0ull, vB23 = 0ull;
#pragma unroll
        for (int c = 0; c < 9; c++) {
            // Port split: even a-rows via constant datapath, odd via shared.
            ulonglong2 w = (a & 1) ? sT[a * 9 + c] : cT[a * 9 + c];
            ffma2(vA01, w.x, cdA[c]);
            ffma2(vA23, w.y, cdA[c]);
            ffma2(vB01, w.x, cdB[c]);
            ffma2(vB23, w.y, cdB[c]);
        }
        unsigned long long aa = pack_dup(abA[a]);
        unsigned long long bb = pack_dup(abB[a]);
        ffma2(zA01, aa, vA01);
        ffma2(zA23, aa, vA23);
        ffma2(zB01, bb, vB01);
        ffma2(zB23, bb, vB23);
    }

    float z0, z1, z2, z3;
    unpack2(zA01, z0, z1);
    unpack2(zA23, z2, z3);
    out[b0] = make_float4(z0, z1, z2, z3);
    if (hasB) {
        unpack2(zB01, z0, z1);
        unpack2(zB23, z2, z3);
        out[b0 + 1] = make_float4(z0, z1, z2, z3);
    }
}

// ---------------------------------------------------------------------------
extern "C" void kernel_launch(void* const* d_in, const int* in_sizes, int n_in,
                              void* d_out, int out_size) {
    const float* inputs  = (const float*)d_in[0];
    const float* weights = (const float*)d_in[1];
    if (n_in >= 2 && in_sizes[0] == 24) {  // defensive: identify by size
        weights = (const float*)d_in[0];
        inputs  = (const float*)d_in[1];
    }
    int nb = out_size / 4;  // samples

    // Constant symbol's backing store (query only — no allocation).
    void* cT_addr = nullptr;
    cudaGetSymbolAddress(&cT_addr, cT);

    setup_kernel<<<1, 256>>>(weights, (float4*)cT_addr);

    int pairs = (nb + 1) / 2;
    int threads = 128;
    int blocks = (pairs + threads - 1) / threads;
    qlayer_kernel<<<blocks, threads>>>((const float4*)inputs, (float4*)d_out, nb);
}

// round 13
// speedup vs baseline: 1.1029x; 1.1029x over previous
#include <cuda_runtime.h>
#include <cuda_bf16.h>

// ---------------------------------------------------------------------------
// QuantumLayer: 4 qubits, 2 variational layers, B = 1e6.
//
// z_q(b) = sum_{t in 3^4} T_q[t] * prod_q basis_{t_q}(x_q),
//   basis = (1, cos x_q, sin x_q);  T[81][4] depends only on weights.
//
// Node 1 (setup, 1 block x 256): barrier-pipelined gate engine (R11) —
//   writes T into the __constant__ backing store.
// Node 2 (main): NS=2 contraction via the constant datapath. Uses the
//   basis identities cd[0]=1 and ab[0]=1 to initialize accumulators by
//   register alias / MOV instead of ffma2: 360 -> 320 fma-pipe ops/thread.
// ---------------------------------------------------------------------------

#define DIM 16

__constant__ ulonglong2 cT[81];    // .x = packed (T0,T1), .y = packed (T2,T3)

// ---------------------------------------------------------------------------
// Setup kernel: one block, 256 threads, barrier-pipelined (R11, proven).
// ---------------------------------------------------------------------------
__global__ void __launch_bounds__(256)
setup_kernel(const float* __restrict__ weights, float4* __restrict__ t_out) {
    __shared__ float sRe[DIM][DIM + 1];   // [col k][row j] = Re(U[j][k]), padded
    __shared__ float sIm[DIM][DIM + 1];
    __shared__ float sG[8][8];            // per (l,q): composed 2x2 complex gate
    __shared__ float sA[4][256];          // A_q[k*16+k']
    int tid = threadIdx.x;

    // ---- Stage 0: compose G = RZ*RY*RX for the 8 (l,q) gates; init U=I ----
    if (tid < 8) {
        float thx = weights[tid * 3 + 0];
        float thy = weights[tid * 3 + 1];
        float thz = weights[tid * 3 + 2];
        float cx, sx, cy, sy, cz, sz;
        __sincosf(0.5f * thx, &sx, &cx);
        __sincosf(0.5f * thy, &sy, &cy);
        __sincosf(0.5f * thz, &sz, &cz);
        // M = RY * RX
        float m00r = cy * cx,  m00i =  sy * sx;
        float m01r = -sy * cx, m01i = -cy * sx;
        float m10r =  sy * cx, m10i = -cy * sx;
        float m11r =  cy * cx, m11i = -sy * sx;
        // G row0 = (cz - i sz) * m0?,  row1 = (cz + i sz) * m1?
        sG[tid][0] = cz * m00r + sz * m00i;  sG[tid][1] = cz * m00i - sz * m00r;
        sG[tid][2] = cz * m01r + sz * m01i;  sG[tid][3] = cz * m01i - sz * m01r;
        sG[tid][4] = cz * m10r - sz * m10i;  sG[tid][5] = cz * m10i + sz * m10r;
        sG[tid][6] = cz * m11r - sz * m11i;  sG[tid][7] = cz * m11i + sz * m11r;
    }
    {   // identity init: thread t = (k, j)
        int k = tid >> 4, j = tid & 15;
        sRe[k][j] = (j == k) ? 1.0f : 0.0f;
        sIm[k][j] = 0.0f;
    }
    __syncthreads();

    // ---- Layers: 4 gate stages each, then one permutation stage ----------
#pragma unroll
    for (int l = 0; l < 2; l++) {
#pragma unroll
        for (int q = 0; q < 4; q++) {
            if (tid < 128) {
                const int mask = 8 >> q;
                int k = tid >> 3, rr = tid & 7;
                int j0 = ((rr & ~(mask - 1)) << 1) | (rr & (mask - 1));
                int j1 = j0 | mask;
                const float* G = sG[l * 4 + q];
                float a0r = sRe[k][j0], a0i = sIm[k][j0];
                float a1r = sRe[k][j1], a1i = sIm[k][j1];
                sRe[k][j0] = G[0]*a0r - G[1]*a0i + G[2]*a1r - G[3]*a1i;
                sIm[k][j0] = G[0]*a0i + G[1]*a0r + G[2]*a1i + G[3]*a1r;
                sRe[k][j1] = G[4]*a0r - G[5]*a0i + G[6]*a1r - G[7]*a1i;
                sIm[k][j1] = G[4]*a0i + G[5]*a0r + G[6]*a1i + G[7]*a1r;
            }
            __syncthreads();
        }
        // CNOT ring (0,1),(1,2),(2,3),(3,0) folded into one permutation.
        {
            int k = tid >> 4, j = tid & 15;
            float vr = sRe[k][j], vi = sIm[k][j];
            int jp = j;
#pragma unroll
            for (int e = 0; e < 4; e++) {
                int cm = 8 >> e, tm = 8 >> ((e + 1) & 3);
                if (jp & cm) jp ^= tm;
            }
            __syncthreads();
            sRe[k][jp] = vr;
            sIm[k][jp] = vi;
            __syncthreads();
        }
    }

    // ---- Fold encoding phase (-i)^popc(k) into column k -------------------
    {
        int k = tid >> 4, j = tid & 15;
        int pc = __popc(k) & 3;
        float pr = (pc == 0) ? 1.0f : (pc == 2) ? -1.0f : 0.0f;
        float pi = (pc == 1) ? -1.0f : (pc == 3) ? 1.0f : 0.0f;
        float vr = sRe[k][j], vi = sIm[k][j];
        sRe[k][j] = vr * pr - vi * pi;
        sIm[k][j] = vr * pi + vi * pr;
    }
    __syncthreads();

    // ---- Phase 2: thread (k,k') computes A_q[k,k'] ------------------------
    {
        int k = tid >> 4, kp = tid & 15;
        float a0 = 0.f, a1 = 0.f, a2 = 0.f, a3 = 0.f;
#pragma unroll
        for (int j = 0; j < DIM; j++) {
            float p = sRe[k][j] * sRe[kp][j] + sIm[k][j] * sIm[kp][j];
            a0 += (j & 8) ? -p : p;
            a1 += (j & 4) ? -p : p;
            a2 += (j & 2) ? -p : p;
            a3 += (j & 1) ? -p : p;
        }
        sA[0][tid] = a0; sA[1][tid] = a1; sA[2][tid] = a2; sA[3][tid] = a3;
    }
    __syncthreads();

    // ---- Phase 3: threads 0-80 compute T[t] -> constant backing -----------
    if (tid < 81) {
        int t0 = tid / 27, t1 = (tid / 9) % 3, t2 = (tid / 3) % 3, t3 = tid % 3;
        int mix = 0, sgn = 0;
        if (t0 == 2) mix |= 8; else if (t0 == 1) sgn |= 8;
        if (t1 == 2) mix |= 4; else if (t1 == 1) sgn |= 4;
        if (t2 == 2) mix |= 2; else if (t2 == 1) sgn |= 2;
        if (t3 == 2) mix |= 1; else if (t3 == 1) sgn |= 1;

        float r0 = 0.f, r1 = 0.f, r2 = 0.f, r3 = 0.f;
#pragma unroll
        for (int k = 0; k < DIM; k++) {
            int idx = k * DIM + (k ^ mix);
            float s = (__popc(k & sgn) & 1) ? -1.0f : 1.0f;
            r0 += s * sA[0][idx];
            r1 += s * sA[1][idx];
            r2 += s * sA[2][idx];
            r3 += s * sA[3][idx];
        }
        const float sc = 1.0f / 16.0f;
        t_out[tid] = make_float4(r0 * sc, r1 * sc, r2 * sc, r3 * sc);
    }
}

// ---------------------------------------------------------------------------
// Packed f32x2 helpers
// ---------------------------------------------------------------------------
__device__ __forceinline__ void ffma2(unsigned long long& d,
                                      unsigned long long a,
                                      unsigned long long b) {
    asm("fma.rn.f32x2 %0, %1, %2, %0;" : "+l"(d) : "l"(a), "l"(b));
}

__device__ __forceinline__ unsigned long long pack_dup(float v) {
    unsigned long long out;
    unsigned int u = __float_as_uint(v);
    asm("mov.b64 %0, {%1, %1};" : "=l"(out) : "r"(u));
    return out;
}

__device__ __forceinline__ void unpack2(unsigned long long v, float& lo, float& hi) {
    unsigned int a, b;
    asm("mov.b64 {%0, %1}, %2;" : "=r"(a), "=r"(b) : "l"(v));
    lo = __uint_as_float(a);
    hi = __uint_as_float(b);
}

// ---------------------------------------------------------------------------
// Main kernel: 2 samples/thread; const-path T; accumulators initialized
// from the c=0 / a=0 terms (basis value 1) instead of ffma-from-zero.
// ---------------------------------------------------------------------------
__global__ void __launch_bounds__(128)
qlayer_kernel(const float4* __restrict__ in, float4* __restrict__ out, int nb) {
    int p = blockIdx.x * blockDim.x + threadIdx.x;   // pair index
    int b0 = 2 * p;
    if (b0 >= nb) return;
    bool hasB = (b0 + 1) < nb;

    float4 xA = in[b0];
    float4 xB = hasB ? in[b0 + 1] : xA;

    float cA0, sA0, cA1, sA1, cA2, sA2, cA3, sA3;
    __sincosf(xA.x, &sA0, &cA0);
    __sincosf(xA.y, &sA1, &cA1);
    __sincosf(xA.z, &sA2, &cA2);
    __sincosf(xA.w, &sA3, &cA3);
    float cB0, sB0, cB1, sB1, cB2, sB2, cB3, sB3;
    __sincosf(xB.x, &sB0, &cB0);
    __sincosf(xB.y, &sB1, &cB1);
    __sincosf(xB.z, &sB2, &cB2);
    __sincosf(xB.w, &sB3, &cB3);

    // a = 3*t0 + t1 basis of qubits 0,1; index 0 is the constant 1 (skipped).
    float abA[9] = { 1.f, cA1, sA1, cA0, cA0 * cA1, cA0 * sA1, sA0, sA0 * cA1, sA0 * sA1 };
    float abB[9] = { 1.f, cB1, sB1, cB0, cB0 * cB1, cB0 * sB1, sB0, sB0 * cB1, sB0 * sB1 };
    // c = 3*t2 + t3 basis of qubits 2,3; index 0 (=1) handled by accumulator init.
    float cdAs[8] = { cA3, sA3, cA2, cA2 * cA3, cA2 * sA3, sA2, sA2 * cA3, sA2 * sA3 };
    float cdBs[8] = { cB3, sB3, cB2, cB2 * cB3, cB2 * sB3, sB2, sB2 * cB3, sB2 * sB3 };
    unsigned long long cdA[8], cdB[8];
#pragma unroll
    for (int c = 0; c < 8; c++) { cdA[c] = pack_dup(cdAs[c]); cdB[c] = pack_dup(cdBs[c]); }

    unsigned long long zA01, zA23, zB01, zB23;
#pragma unroll
    for (int a = 0; a < 9; a++) {
        // c = 0 term: cd[0] = 1 -> accumulators start at w0 (no ffma2).
        ulonglong2 w0 = cT[a * 9];
        unsigned long long vA01 = w0.x, vA23 = w0.y;
        unsigned long long vB01 = w0.x, vB23 = w0.y;
#pragma unroll
        for (int c = 1; c < 9; c++) {
            ulonglong2 w = cT[a * 9 + c];    // constant/uniform datapath
            ffma2(vA01, w.x, cdA[c - 1]);
            ffma2(vA23, w.y, cdA[c - 1]);
            ffma2(vB01, w.x, cdB[c - 1]);
            ffma2(vB23, w.y, cdB[c - 1]);
        }
        if (a == 0) {
            // ab[0] = 1 -> z initialized by the a=0 row (register rename).
            zA01 = vA01; zA23 = vA23; zB01 = vB01; zB23 = vB23;
        } else {
            unsigned long long aa = pack_dup(abA[a]);
            unsigned long long bb = pack_dup(abB[a]);
            ffma2(zA01, aa, vA01);
            ffma2(zA23, aa, vA23);
            ffma2(zB01, bb, vB01);
            ffma2(zB23, bb, vB23);
        }
    }

    float z0, z1, z2, z3;
    unpack2(zA01, z0, z1);
    unpack2(zA23, z2, z3);
    out[b0] = make_float4(z0, z1, z2, z3);
    if (hasB) {
        unpack2(zB01, z0, z1);
        unpack2(zB23, z2, z3);
        out[b0 + 1] = make_float4(z0, z1, z2, z3);
    }
}

// ---------------------------------------------------------------------------
extern "C" void kernel_launch(void* const* d_in, const int* in_sizes, int n_in,
                              void* d_out, int out_size) {
    const float* inputs  = (const float*)d_in[0];
    const float* weights = (const float*)d_in[1];
    if (n_in >= 2 && in_sizes[0] == 24) {  // defensive: identify by size
        weights = (const float*)d_in[0];
        inputs  = (const float*)d_in[1];
    }
    int nb = out_size / 4;  // samples

    // Constant symbol's backing store (query only — no allocation).
    void* cT_addr = nullptr;
    cudaGetSymbolAddress(&cT_addr, cT);

    setup_kernel<<<1, 256>>>(weights, (float4*)cT_addr);

    int pairs = (nb + 1) / 2;
    int threads = 128;
    int blocks = (pairs + threads - 1) / threads;
    qlayer_kernel<<<blocks, threads>>>((const float4*)inputs, (float4*)d_out, nb);
}